// round 8
// baseline (speedup 1.0000x reference)
#include <cuda_runtime.h>
#include <cuda_bf16.h>
#include <cstdint>

// Problem shape constants (fixed by the reference).
#define BB 2
#define LL 2048
#define DD 1024
#define HH 16
#define HD 64
#define ROWS (BB*LL)            // 4096
#define QKV_N (3*DD)            // 3072
#define BLD (BB*LL*DD)          // 4194304
#define WQKV_SZ (QKV_N*DD)      // 3145728
#define WOUT_SZ (DD*DD)         // 1048576

// ---------------------------------------------------------------------------
// Scratch (alloc-free rule: __device__ globals)
// ---------------------------------------------------------------------------
__device__ float g_xr  [BLD];
__device__ float g_wqkv[WQKV_SZ];
__device__ float g_wout[WOUT_SZ];
__device__ float g_qkv [ROWS * QKV_N];
__device__ float g_q   [BLD];
__device__ float g_k   [BLD];
__device__ float g_v   [BLD];
__device__ float g_ctx [BLD];

// ---------------------------------------------------------------------------
// Helpers
// ---------------------------------------------------------------------------
__device__ __forceinline__ uint32_t f2tf(float f) {
    uint32_t r;
    asm("cvt.rna.tf32.f32 %0, %1;" : "=r"(r) : "f"(f));
    return r;
}

__device__ __forceinline__ uint32_t smem_u32(const void* p) {
    uint32_t a;
    asm("{ .reg .u64 t; cvta.to.shared.u64 t, %1; cvt.u32.u64 %0, t; }"
        : "=r"(a) : "l"(p));
    return a;
}

// m16n8k8 tf32 mma (.row.col)
__device__ __forceinline__ void mma8(float* c, const uint32_t* a, const uint32_t* b) {
    asm volatile(
        "mma.sync.aligned.m16n8k8.row.col.f32.tf32.tf32.f32 "
        "{%0,%1,%2,%3}, {%4,%5,%6,%7}, {%8,%9}, {%0,%1,%2,%3};"
        : "+f"(c[0]), "+f"(c[1]), "+f"(c[2]), "+f"(c[3])
        : "r"(a[0]), "r"(a[1]), "r"(a[2]), "r"(a[3]), "r"(b[0]), "r"(b[1]));
}

// ldmatrix x4 (b32 data viewed as b16 pairs; mapping matches mma frags)
__device__ __forceinline__ void ldsm4(uint32_t* r, uint32_t addr) {
    asm volatile(
        "ldmatrix.sync.aligned.m8n8.x4.shared.b16 {%0,%1,%2,%3}, [%4];"
        : "=r"(r[0]), "=r"(r[1]), "=r"(r[2]), "=r"(r[3]) : "r"(addr));
}

#define CP16(dst, src) \
    asm volatile("cp.async.cg.shared.global [%0], [%1], 16;" :: "r"(dst), "l"(src))
#define CP_COMMIT() asm volatile("cp.async.commit_group;" ::: "memory")
#define CP_WAIT(n)  asm volatile("cp.async.wait_group %0;" :: "n"(n) : "memory")

// ---------------------------------------------------------------------------
// Fused round-to-tf32 of x, Wqkv, Wout
// ---------------------------------------------------------------------------
#define RND_TOTAL4 ((BLD + WQKV_SZ + WOUT_SZ) / 4)

__global__ __launch_bounds__(256) void round_all(
    const float4* __restrict__ x,   float4* __restrict__ xr,
    const float4* __restrict__ wq,  float4* __restrict__ wqr,
    const float4* __restrict__ wo,  float4* __restrict__ wor)
{
    int i = blockIdx.x * 256 + threadIdx.x;
    if (i >= RND_TOTAL4) return;
    const float4* src; float4* dst;
    if (i < BLD/4)                       { src = x;  dst = xr;  }
    else if (i < (BLD + WQKV_SZ)/4)      { src = wq; dst = wqr; i -= BLD/4; }
    else                                 { src = wo; dst = wor; i -= (BLD + WQKV_SZ)/4; }
    float4 v = src[i];
    float4 o;
    o.x = __uint_as_float(f2tf(v.x));
    o.y = __uint_as_float(f2tf(v.y));
    o.z = __uint_as_float(f2tf(v.z));
    o.w = __uint_as_float(f2tf(v.w));
    dst[i] = o;
}

// ---------------------------------------------------------------------------
// tf32 mma.sync NT GEMM (unchanged): 128x128 CTA tile, BK=32, 256 threads,
// ldmatrix fragments, smem stride 36.
// ---------------------------------------------------------------------------
#define GSTR 36
#define GEMM_SMEM (2 * 2 * 128 * GSTR * 4)

__global__ __launch_bounds__(256) void gemm_mma(
    const float* __restrict__ A, const float* __restrict__ B,
    const float* __restrict__ bias, float* __restrict__ C,
    int N, int K)
{
    extern __shared__ float sm[];
    float* As = sm;
    float* Bs = sm + 2 * 128 * GSTR;
    const uint32_t As_u = smem_u32(As);
    const uint32_t Bs_u = smem_u32(Bs);

    const int tid  = threadIdx.x;
    const int lane = tid & 31;
    const int wid  = tid >> 5;
    const int wm   = wid & 1;
    const int wn   = wid >> 1;
    const int lq   = lane >> 2;
    const int ls   = lane & 3;
    const int s    = lane >> 3;
    const int srow = lane & 7;

    const uint32_t a_lane =
        (uint32_t)(((wm * 64) + (s & 1) * 8 + srow) * GSTR + (s >> 1) * 4) * 4;
    const uint32_t b_lane =
        (uint32_t)(((wn * 32) + (s >> 1) * 8 + srow) * GSTR + (s & 1) * 4) * 4;

    const float* Ab = A + (size_t)(blockIdx.y * 128) * K;
    const float* Bb = B + (size_t)(blockIdx.x * 128) * K;
    const int KS = K >> 5;

    float acc[4][4][4];
#pragma unroll
    for (int mt = 0; mt < 4; ++mt)
#pragma unroll
        for (int nt = 0; nt < 4; ++nt)
#pragma unroll
            for (int r = 0; r < 4; ++r) acc[mt][nt][r] = 0.f;

#define GEMM_LOAD(ks, db)                                                     \
    {                                                                         \
        const int k0 = (ks) * 32;                                             \
        const uint32_t dA = As_u + (db) * 128 * GSTR * 4;                     \
        const uint32_t dB = Bs_u + (db) * 128 * GSTR * 4;                     \
        _Pragma("unroll")                                                     \
        for (int i = 0; i < 4; ++i) {                                         \
            const int c   = tid + i * 256;                                    \
            const int row = c >> 3;                                           \
            const int cc  = (c & 7) * 4;                                      \
            const uint32_t off = (uint32_t)(row * GSTR + cc) * 4;             \
            CP16(dA + off, Ab + (size_t)row * K + k0 + cc);                   \
            CP16(dB + off, Bb + (size_t)row * K + k0 + cc);                   \
        }                                                                     \
        CP_COMMIT();                                                          \
    }

    GEMM_LOAD(0, 0);

    for (int ks = 0; ks < KS; ++ks) {
        const int db = ks & 1;
        if (ks + 1 < KS) { GEMM_LOAD(ks + 1, db ^ 1); CP_WAIT(1); }
        else             { CP_WAIT(0); }
        __syncthreads();

        const uint32_t Ad_u = As_u + db * 128 * GSTR * 4;
        const uint32_t Bd_u = Bs_u + db * 128 * GSTR * 4;

#pragma unroll
        for (int kb = 0; kb < 4; ++kb) {
            uint32_t a[4][4], b[2][4];
#pragma unroll
            for (int mt = 0; mt < 4; ++mt)
                ldsm4(a[mt], Ad_u + a_lane + (uint32_t)(mt * 16 * GSTR + kb * 8) * 4);
#pragma unroll
            for (int ntp = 0; ntp < 2; ++ntp)
                ldsm4(b[ntp], Bd_u + b_lane + (uint32_t)(ntp * 16 * GSTR + kb * 8) * 4);
#pragma unroll
            for (int mt = 0; mt < 4; ++mt)
#pragma unroll
                for (int nt = 0; nt < 4; ++nt)
                    mma8(acc[mt][nt], a[mt], &b[nt >> 1][(nt & 1) * 2]);
        }
        __syncthreads();
    }

    const int row_base = blockIdx.y * 128 + wm * 64;
    const int col_base = blockIdx.x * 128 + wn * 32;
#pragma unroll
    for (int mt = 0; mt < 4; ++mt) {
        const int r0 = row_base + mt * 16 + lq;
#pragma unroll
        for (int nt = 0; nt < 4; ++nt) {
            const int cn = col_base + nt * 8 + ls * 2;
            const float2 bb = *(const float2*)(bias + cn);
            float2 o0, o1;
            o0.x = acc[mt][nt][0] + bb.x;  o0.y = acc[mt][nt][1] + bb.y;
            o1.x = acc[mt][nt][2] + bb.x;  o1.y = acc[mt][nt][3] + bb.y;
            *(float2*)(C + (size_t)r0 * N + cn)       = o0;
            *(float2*)(C + (size_t)(r0 + 8) * N + cn) = o1;
        }
    }
}

// ---------------------------------------------------------------------------
// RoPE + head scatter (unchanged).
// ---------------------------------------------------------------------------
__global__ __launch_bounds__(256) void rope_scatter(
    const float* __restrict__ qkv,
    float* __restrict__ qh, float* __restrict__ kh, float* __restrict__ vh,
    float* __restrict__ kout, float* __restrict__ vout)
{
    const int t = blockIdx.x * blockDim.x + threadIdx.x;
    const int d = t & 31;
    const int h = (t >> 5) & 15;
    const int l = (t >> 9) & 2047;
    const int b = t >> 20;

    const float* base = qkv + (size_t)(b * LL + l) * QKV_N;

    const float inv = __expf(-(float)d * (9.210340371976184f / 32.f));
    const float ang = (float)l * inv;
    float sn, cs;
    sincosf(ang, &sn, &cs);

    const size_t ob = ((size_t)((b * HH + h) * LL + l)) * HD;

    const float q1 = base[h*HD + d], q2 = base[h*HD + d + 32];
    qh[ob + d]      = __uint_as_float(f2tf((q1 * cs - q2 * sn) * 0.125f));
    qh[ob + d + 32] = __uint_as_float(f2tf((q1 * sn + q2 * cs) * 0.125f));

    const float k1 = base[DD + h*HD + d], k2 = base[DD + h*HD + d + 32];
    const float kr1 = k1 * cs - k2 * sn;
    const float kr2 = k1 * sn + k2 * cs;
    kout[ob + d]      = kr1;
    kout[ob + d + 32] = kr2;
    kh[ob + d]        = __uint_as_float(f2tf(kr1));
    kh[ob + d + 32]   = __uint_as_float(f2tf(kr2));

    const float v1 = base[2*DD + h*HD + d], v2 = base[2*DD + h*HD + d + 32];
    vout[ob + d]      = v1;
    vout[ob + d + 32] = v2;
    vh[ob + d]        = __uint_as_float(f2tf(v1));
    vh[ob + d + 32]   = __uint_as_float(f2tf(v2));
}

// ---------------------------------------------------------------------------
// Flash attention v5: Br=64, Bc=128, 512 threads (16 warps = 4 row x 4 col).
// Warp (wr=wid&3, wc=wid>>2): rows wr*16..+16, K-tokens wc*32..+32 of each
// 128-token tile. Per-warp independent online softmax over its token subset;
// 4-way split-KV combine in the epilogue.
// smem: Ks[2][128*FSTR] | Vt[2][64*VSTR] | Ps[16][16*PSTR] | cm[256] | cl[256]
// Epilogue 'ac' (3 x 64 x 66) aliases the Ks region (dead by then).
// ---------------------------------------------------------------------------
#define FSTR 68
#define VSTR 132
#define PSTR 36
#define VT_OFFF (2*128*FSTR)                 // 17408
#define PS_OFFF (VT_OFFF + 2*64*VSTR)        // 34304
#define CM_OFFF (PS_OFFF + 16*16*PSTR)       // 43520
#define CL_OFFF (CM_OFFF + 256)
#define FLASH_SMEM ((CL_OFFF + 256) * 4)     // 176128 B

__global__ __launch_bounds__(512) void flash_mma(
    const float* __restrict__ Q, const float* __restrict__ K,
    const float* __restrict__ V, float* __restrict__ ctx)
{
    extern __shared__ float sm[];
    float* Ks = sm;
    float* Vt = sm + VT_OFFF;
    float* Ps = sm + PS_OFFF;
    float* cm = sm + CM_OFFF;
    float* cl = sm + CL_OFFF;
    float* ac = sm;                      // epilogue alias of Ks, stride 66
    const uint32_t Ks_u = smem_u32(Ks);
    const uint32_t Vt_u = smem_u32(Vt);
    const uint32_t Ps_u = smem_u32(Ps);

    const int qi   = gridDim.x - 1 - blockIdx.x;   // heavy tiles first
    const int bh   = blockIdx.y;
    const int tid  = threadIdx.x;
    const int lane = tid & 31;
    const int wid  = tid >> 5;           // 0..15
    const int wr   = wid & 3;            // row group (4 x 16 rows)
    const int wc   = wid >> 2;           // col group (4 x 32 tokens)
    const int lq   = lane >> 2;
    const int ls   = lane & 3;
    const int s    = lane >> 3;
    const int srow = lane & 7;
    const int rrow = wr * 16 + lq;       // rows rrow, rrow+8 (0..63)

    // ldmatrix lane offsets (bytes)
    const uint32_t bk_lane =
        (uint32_t)(((s >> 1) * 8 + srow) * FSTR + (s & 1) * 4) * 4;
    const uint32_t bv_lane =
        (uint32_t)(((s >> 1) * 8 + srow) * VSTR + (s & 1) * 4) * 4;
    const uint32_t ap_lane =
        (uint32_t)(((s & 1) * 8 + srow) * PSTR + (s >> 1) * 4) * 4;
    const uint32_t Psw_u = Ps_u + (uint32_t)(wid * 16 * PSTR) * 4;
    float* Psw = Ps + wid * 16 * PSTR;

    const float* Qb = Q + ((size_t)bh * LL + qi * 64) * HD;
    const float* Kb = K + (size_t)bh * LL * HD;
    const float* Vb = V + (size_t)bh * LL * HD;

    // K tile loader: 128 tokens x 64 dims, 512 threads -> 4 cp.async each
#define FL_LOAD_K(dst_u, src)                                                 \
    {                                                                         \
        _Pragma("unroll")                                                     \
        for (int i = 0; i < 4; ++i) {                                         \
            const int c   = tid + i * 512;                                    \
            const int row = c >> 4;                                           \
            const int cc  = (c & 15) * 4;                                     \
            CP16((dst_u) + (uint32_t)(row * FSTR + cc) * 4,                   \
                 (src) + (size_t)row * HD + cc);                              \
        }                                                                     \
    }

    const int vtok = tid & 127;          // token 0..127
    const int vseg = tid >> 7;           // 0..3 -> 16 dims each

    float4 vr[4];
#define FL_LDG_V(jt)                                                          \
    {                                                                         \
        const float* vb = Vb + ((size_t)(jt) * 128 + vtok) * HD + vseg * 16;  \
        _Pragma("unroll")                                                     \
        for (int i = 0; i < 4; ++i) vr[i] = *(const float4*)(vb + i * 4);     \
    }

#define FL_STS_V(db)                                                          \
    {                                                                         \
        float* vt = Vt + (db) * 64 * VSTR;                                    \
        _Pragma("unroll")                                                     \
        for (int i = 0; i < 4; ++i) {                                         \
            const int c0 = vseg * 16 + i * 4;                                 \
            vt[(c0 + 0) * VSTR + vtok] = vr[i].x;                             \
            vt[(c0 + 1) * VSTR + vtok] = vr[i].y;                             \
            vt[(c0 + 2) * VSTR + vtok] = vr[i].z;                             \
            vt[(c0 + 3) * VSTR + vtok] = vr[i].w;                             \
        }                                                                     \
    }

    // prologue
    FL_LOAD_K(Ks_u, Kb);
    CP_COMMIT();
    FL_LDG_V(0);

    uint32_t qf[8][4];
#pragma unroll
    for (int kb = 0; kb < 8; ++kb) {
        const int k = kb * 8 + ls;
        qf[kb][0] = __float_as_uint(Qb[(size_t)rrow * HD + k]);
        qf[kb][1] = __float_as_uint(Qb[(size_t)(rrow + 8) * HD + k]);
        qf[kb][2] = __float_as_uint(Qb[(size_t)rrow * HD + k + 4]);
        qf[kb][3] = __float_as_uint(Qb[(size_t)(rrow + 8) * HD + k + 4]);
    }

    float acc[8][4];
#pragma unroll
    for (int nt = 0; nt < 8; ++nt)
#pragma unroll
        for (int r = 0; r < 4; ++r) acc[nt][r] = 0.f;
    float m0 = -1e30f, m1 = -1e30f, l0 = 0.f, l1 = 0.f;

    const int ntiles = (qi >> 1) + 1;    // 128-token tiles covering causal span
    const int jtmax  = ntiles - 1;

    for (int jt = 0; jt <= jtmax; ++jt) {
        const int db = jt & 1;
        CP_WAIT(0);
        FL_STS_V(db);
        __syncthreads();

        if (jt < jtmax) {
            FL_LOAD_K(Ks_u + (uint32_t)((db ^ 1) * 128 * FSTR) * 4,
                      Kb + (size_t)(jt + 1) * 128 * HD);
            CP_COMMIT();
            FL_LDG_V(jt + 1);
        }

        // ---- S = Q K^T on this warp's 32 tokens ----
        float sc[4][4];
#pragma unroll
        for (int nt = 0; nt < 4; ++nt)
#pragma unroll
            for (int r = 0; r < 4; ++r) sc[nt][r] = 0.f;

        const uint32_t Kd_u = Ks_u + (uint32_t)(db * 128 * FSTR) * 4
                            + (uint32_t)(wc * 32 * FSTR) * 4 + bk_lane;
#pragma unroll
        for (int kb = 0; kb < 8; ++kb) {
#pragma unroll
            for (int ntp = 0; ntp < 2; ++ntp) {
                uint32_t b[4];
                ldsm4(b, Kd_u + (uint32_t)(ntp * 16 * FSTR + kb * 8) * 4);
                mma8(sc[ntp * 2],     qf[kb], b);
                mma8(sc[ntp * 2 + 1], qf[kb], b + 2);
            }
        }

        // ---- causal mask (only the final tile can touch the diagonal) ----
        if (jt == jtmax) {
            const int rg0 = qi * 64 + rrow;
            const int cbase = jt * 128 + wc * 32;
#pragma unroll
            for (int nt = 0; nt < 4; ++nt) {
                const int cg = cbase + nt * 8 + ls * 2;
                if (cg > rg0)         sc[nt][0] += -1000000000.0f;
                if (cg + 1 > rg0)     sc[nt][1] += -1000000000.0f;
                if (cg > rg0 + 8)     sc[nt][2] += -1000000000.0f;
                if (cg + 1 > rg0 + 8) sc[nt][3] += -1000000000.0f;
            }
        }

        // ---- row max over this warp's 32 tokens (quad shfl) ----
        float mx0 = sc[0][0], mx1 = sc[0][2];
#pragma unroll
        for (int nt = 0; nt < 4; ++nt) {
            mx0 = fmaxf(mx0, fmaxf(sc[nt][0], sc[nt][1]));
            mx1 = fmaxf(mx1, fmaxf(sc[nt][2], sc[nt][3]));
        }
        mx0 = fmaxf(mx0, __shfl_xor_sync(0xffffffffu, mx0, 1));
        mx0 = fmaxf(mx0, __shfl_xor_sync(0xffffffffu, mx0, 2));
        mx1 = fmaxf(mx1, __shfl_xor_sync(0xffffffffu, mx1, 1));
        mx1 = fmaxf(mx1, __shfl_xor_sync(0xffffffffu, mx1, 2));

        const float mn0 = fmaxf(m0, mx0);
        const float mn1 = fmaxf(m1, mx1);
        const float al0 = __expf(m0 - mn0);
        const float al1 = __expf(m1 - mn1);
        m0 = mn0; m1 = mn1;

        // ---- P = exp(S - m), round, store to own Ps slice; row sums ----
        float rs0 = 0.f, rs1 = 0.f;
#pragma unroll
        for (int nt = 0; nt < 4; ++nt) {
            const float p0 = __expf(sc[nt][0] - mn0);
            const float p1 = __expf(sc[nt][1] - mn0);
            const float p2 = __expf(sc[nt][2] - mn1);
            const float p3 = __expf(sc[nt][3] - mn1);
            rs0 += p0 + p1;  rs1 += p2 + p3;
            uint2 w0, w1;
            w0.x = f2tf(p0); w0.y = f2tf(p1);
            w1.x = f2tf(p2); w1.y = f2tf(p3);
            const int cc = nt * 8 + ls * 2;
            *(uint2*)(Psw + lq * PSTR + cc)       = w0;
            *(uint2*)(Psw + (lq + 8) * PSTR + cc) = w1;
        }
        rs0 += __shfl_xor_sync(0xffffffffu, rs0, 1);
        rs0 += __shfl_xor_sync(0xffffffffu, rs0, 2);
        rs1 += __shfl_xor_sync(0xffffffffu, rs1, 1);
        rs1 += __shfl_xor_sync(0xffffffffu, rs1, 2);
        l0 = l0 * al0 + rs0;
        l1 = l1 * al1 + rs1;

#pragma unroll
        for (int nt = 0; nt < 8; ++nt) {
            acc[nt][0] *= al0; acc[nt][1] *= al0;
            acc[nt][2] *= al1; acc[nt][3] *= al1;
        }
        __syncwarp();                    // Ps slice visible to own ldmatrix

        // ---- O += P V over this warp's 32 tokens, full 64 head dims ----
        const uint32_t Vd_u = Vt_u + (uint32_t)(db * 64 * VSTR) * 4 + bv_lane;
#pragma unroll
        for (int kb = 0; kb < 4; ++kb) {
            uint32_t a[4];
            ldsm4(a, Psw_u + ap_lane + (uint32_t)(kb * 8) * 4);
#pragma unroll
            for (int ntp = 0; ntp < 4; ++ntp) {
                uint32_t b[4];
                ldsm4(b, Vd_u +
                      (uint32_t)(ntp * 16 * VSTR + wc * 32 + kb * 8) * 4);
                mma8(acc[ntp * 2],     a, b);
                mma8(acc[ntp * 2 + 1], a, b + 2);
            }
        }
        __syncwarp();
    }

    // ---- epilogue: 4-way split-KV combine across column groups ----
    if (ls == 0) {
        cm[wc * 64 + rrow]     = m0;  cm[wc * 64 + rrow + 8] = m1;
        cl[wc * 64 + rrow]     = l0;  cl[wc * 64 + rrow + 8] = l1;
    }
    __syncthreads();                     // also fences all loop smem reads

    float M0 = -1e30f, M1 = -1e30f;
#pragma unroll
    for (int g = 0; g < 4; ++g) {
        M0 = fmaxf(M0, cm[g * 64 + rrow]);
        M1 = fmaxf(M1, cm[g * 64 + rrow + 8]);
    }
    float lt0 = 0.f, lt1 = 0.f;
#pragma unroll
    for (int g = 0; g < 4; ++g) {
        lt0 += cl[g * 64 + rrow]     * __expf(cm[g * 64 + rrow]     - M0);
        lt1 += cl[g * 64 + rrow + 8] * __expf(cm[g * 64 + rrow + 8] - M1);
    }
    const float s0 = __expf(m0 - M0);
    const float s1 = __expf(m1 - M1);

    if (wc != 0) {                       // publish scaled partial O
        float* acg = ac + (wc - 1) * 64 * 66;
#pragma unroll
        for (int nt = 0; nt < 8; ++nt) {
            const int cc = nt * 8 + ls * 2;
            float2 w0, w1;
            w0.x = acc[nt][0] * s0; w0.y = acc[nt][1] * s0;
            w1.x = acc[nt][2] * s1; w1.y = acc[nt][3] * s1;
            *(float2*)(acg + rrow * 66 + cc)       = w0;
            *(float2*)(acg + (rrow + 8) * 66 + cc) = w1;
        }
    }
    __syncthreads();

    if (wc == 0) {
        const float inv0 = 1.f / lt0;
        const float inv1 = 1.f / lt1;
        const int b = bh >> 4;
        const int h = bh & 15;
        const int r0 = qi * 64 + rrow;
#pragma unroll
        for (int nt = 0; nt < 8; ++nt) {
            const int cc = nt * 8 + ls * 2;
            float a0 = acc[nt][0] * s0, a1 = acc[nt][1] * s0;
            float a2 = acc[nt][2] * s1, a3 = acc[nt][3] * s1;
#pragma unroll
            for (int g = 0; g < 3; ++g) {
                const float* acg = ac + g * 64 * 66;
                const float2 p0 = *(const float2*)(acg + rrow * 66 + cc);
                const float2 p1 = *(const float2*)(acg + (rrow + 8) * 66 + cc);
                a0 += p0.x; a1 += p0.y; a2 += p1.x; a3 += p1.y;
            }
            const int cn = h * HD + cc;
            uint2 o0, o1;
            o0.x = f2tf(a0 * inv0); o0.y = f2tf(a1 * inv0);
            o1.x = f2tf(a2 * inv1); o1.y = f2tf(a3 * inv1);
            *(uint2*)(ctx + (size_t)(b * LL + r0) * DD + cn)     = o0;
            *(uint2*)(ctx + (size_t)(b * LL + r0 + 8) * DD + cn) = o1;
        }
    }
}

// ---------------------------------------------------------------------------
// Launch
// ---------------------------------------------------------------------------
extern "C" void kernel_launch(void* const* d_in, const int* in_sizes, int n_in,
                              void* d_out, int out_size)
{
    const float* x       = (const float*)d_in[0];
    const float* Wqkv_w  = (const float*)d_in[2];
    const float* Wqkv_b  = (const float*)d_in[3];
    const float* Wout_w  = (const float*)d_in[4];
    const float* Wout_b  = (const float*)d_in[5];

    float* out  = (float*)d_out;
    float* kout = out + BLD;
    float* vout = kout + BLD;

    float *xr, *wqkv, *wout_r, *qkv, *qh, *kh, *vh, *ctx;
    cudaGetSymbolAddress((void**)&xr,     g_xr);
    cudaGetSymbolAddress((void**)&wqkv,   g_wqkv);
    cudaGetSymbolAddress((void**)&wout_r, g_wout);
    cudaGetSymbolAddress((void**)&qkv,    g_qkv);
    cudaGetSymbolAddress((void**)&qh,     g_q);
    cudaGetSymbolAddress((void**)&kh,     g_k);
    cudaGetSymbolAddress((void**)&vh,     g_v);
    cudaGetSymbolAddress((void**)&ctx,    g_ctx);

    cudaFuncSetAttribute(gemm_mma,
                         cudaFuncAttributeMaxDynamicSharedMemorySize, GEMM_SMEM);
    cudaFuncSetAttribute(flash_mma,
                         cudaFuncAttributeMaxDynamicSharedMemorySize, FLASH_SMEM);

    round_all<<<(RND_TOTAL4 + 255) / 256, 256>>>(
        (const float4*)x, (float4*)xr,
        (const float4*)Wqkv_w, (float4*)wqkv,
        (const float4*)Wout_w, (float4*)wout_r);

    gemm_mma<<<dim3(QKV_N / 128, ROWS / 128), 256, GEMM_SMEM>>>(
        xr, wqkv, Wqkv_b, qkv, QKV_N, DD);

    rope_scatter<<<(BB * LL * HH * 32) / 256, 256>>>(qkv, qh, kh, vh, kout, vout);

    flash_mma<<<dim3(LL / 64, BB * HH), 512, FLASH_SMEM>>>(qh, kh, vh, ctx);

    gemm_mma<<<dim3(DD / 128, ROWS / 128), 256, GEMM_SMEM>>>(
        ctx, wout_r, Wout_b, out, DD, DD);
}

// round 9
// speedup vs baseline: 1.1069x; 1.1069x over previous
#include <cuda_runtime.h>
#include <cuda_bf16.h>
#include <cstdint>

// Problem shape constants (fixed by the reference).
#define BB 2
#define LL 2048
#define DD 1024
#define HH 16
#define HD 64
#define ROWS (BB*LL)            // 4096
#define QKV_N (3*DD)            // 3072
#define BLD (BB*LL*DD)          // 4194304
#define WQKV_SZ (QKV_N*DD)      // 3145728
#define WOUT_SZ (DD*DD)         // 1048576

// ---------------------------------------------------------------------------
// Scratch (alloc-free rule: __device__ globals)
// ---------------------------------------------------------------------------
__device__ float g_xr  [BLD];
__device__ float g_wqkv[WQKV_SZ];
__device__ float g_wout[WOUT_SZ];
__device__ float g_qkv [ROWS * QKV_N];
__device__ float g_q   [BLD];
__device__ float g_k   [BLD];
__device__ float g_v   [BLD];
__device__ float g_ctx [BLD];

// ---------------------------------------------------------------------------
// Helpers
// ---------------------------------------------------------------------------
__device__ __forceinline__ uint32_t f2tf(float f) {
    uint32_t r;
    asm("cvt.rna.tf32.f32 %0, %1;" : "=r"(r) : "f"(f));
    return r;
}

__device__ __forceinline__ uint32_t smem_u32(const void* p) {
    uint32_t a;
    asm("{ .reg .u64 t; cvta.to.shared.u64 t, %1; cvt.u32.u64 %0, t; }"
        : "=r"(a) : "l"(p));
    return a;
}

// m16n8k8 tf32 mma (.row.col)
__device__ __forceinline__ void mma8(float* c, const uint32_t* a, const uint32_t* b) {
    asm volatile(
        "mma.sync.aligned.m16n8k8.row.col.f32.tf32.tf32.f32 "
        "{%0,%1,%2,%3}, {%4,%5,%6,%7}, {%8,%9}, {%0,%1,%2,%3};"
        : "+f"(c[0]), "+f"(c[1]), "+f"(c[2]), "+f"(c[3])
        : "r"(a[0]), "r"(a[1]), "r"(a[2]), "r"(a[3]), "r"(b[0]), "r"(b[1]));
}

// ldmatrix x4 (b32 data viewed as b16 pairs; mapping matches mma frags)
__device__ __forceinline__ void ldsm4(uint32_t* r, uint32_t addr) {
    asm volatile(
        "ldmatrix.sync.aligned.m8n8.x4.shared.b16 {%0,%1,%2,%3}, [%4];"
        : "=r"(r[0]), "=r"(r[1]), "=r"(r[2]), "=r"(r[3]) : "r"(addr));
}

#define CP16(dst, src) \
    asm volatile("cp.async.cg.shared.global [%0], [%1], 16;" :: "r"(dst), "l"(src))
#define CP_COMMIT() asm volatile("cp.async.commit_group;" ::: "memory")
#define CP_WAIT(n)  asm volatile("cp.async.wait_group %0;" :: "n"(n) : "memory")

// ---------------------------------------------------------------------------
// Fused round-to-tf32 of x, Wqkv, Wout
// ---------------------------------------------------------------------------
#define RND_TOTAL4 ((BLD + WQKV_SZ + WOUT_SZ) / 4)

__global__ __launch_bounds__(256) void round_all(
    const float4* __restrict__ x,   float4* __restrict__ xr,
    const float4* __restrict__ wq,  float4* __restrict__ wqr,
    const float4* __restrict__ wo,  float4* __restrict__ wor)
{
    int i = blockIdx.x * 256 + threadIdx.x;
    if (i >= RND_TOTAL4) return;
    const float4* src; float4* dst;
    if (i < BLD/4)                       { src = x;  dst = xr;  }
    else if (i < (BLD + WQKV_SZ)/4)      { src = wq; dst = wqr; i -= BLD/4; }
    else                                 { src = wo; dst = wor; i -= (BLD + WQKV_SZ)/4; }
    float4 v = src[i];
    float4 o;
    o.x = __uint_as_float(f2tf(v.x));
    o.y = __uint_as_float(f2tf(v.y));
    o.z = __uint_as_float(f2tf(v.z));
    o.w = __uint_as_float(f2tf(v.w));
    dst[i] = o;
}

// ---------------------------------------------------------------------------
// tf32 mma.sync NT GEMM (unchanged): 128x128 CTA tile, BK=32, 256 threads,
// ldmatrix fragments, smem stride 36.
// ---------------------------------------------------------------------------
#define GSTR 36
#define GEMM_SMEM (2 * 2 * 128 * GSTR * 4)

__global__ __launch_bounds__(256) void gemm_mma(
    const float* __restrict__ A, const float* __restrict__ B,
    const float* __restrict__ bias, float* __restrict__ C,
    int N, int K)
{
    extern __shared__ float sm[];
    float* As = sm;
    float* Bs = sm + 2 * 128 * GSTR;
    const uint32_t As_u = smem_u32(As);
    const uint32_t Bs_u = smem_u32(Bs);

    const int tid  = threadIdx.x;
    const int lane = tid & 31;
    const int wid  = tid >> 5;
    const int wm   = wid & 1;
    const int wn   = wid >> 1;
    const int lq   = lane >> 2;
    const int ls   = lane & 3;
    const int s    = lane >> 3;
    const int srow = lane & 7;

    const uint32_t a_lane =
        (uint32_t)(((wm * 64) + (s & 1) * 8 + srow) * GSTR + (s >> 1) * 4) * 4;
    const uint32_t b_lane =
        (uint32_t)(((wn * 32) + (s >> 1) * 8 + srow) * GSTR + (s & 1) * 4) * 4;

    const float* Ab = A + (size_t)(blockIdx.y * 128) * K;
    const float* Bb = B + (size_t)(blockIdx.x * 128) * K;
    const int KS = K >> 5;

    float acc[4][4][4];
#pragma unroll
    for (int mt = 0; mt < 4; ++mt)
#pragma unroll
        for (int nt = 0; nt < 4; ++nt)
#pragma unroll
            for (int r = 0; r < 4; ++r) acc[mt][nt][r] = 0.f;

#define GEMM_LOAD(ks, db)                                                     \
    {                                                                         \
        const int k0 = (ks) * 32;                                             \
        const uint32_t dA = As_u + (db) * 128 * GSTR * 4;                     \
        const uint32_t dB = Bs_u + (db) * 128 * GSTR * 4;                     \
        _Pragma("unroll")                                                     \
        for (int i = 0; i < 4; ++i) {                                         \
            const int c   = tid + i * 256;                                    \
            const int row = c >> 3;                                           \
            const int cc  = (c & 7) * 4;                                      \
            const uint32_t off = (uint32_t)(row * GSTR + cc) * 4;             \
            CP16(dA + off, Ab + (size_t)row * K + k0 + cc);                   \
            CP16(dB + off, Bb + (size_t)row * K + k0 + cc);                   \
        }                                                                     \
        CP_COMMIT();                                                          \
    }

    GEMM_LOAD(0, 0);

    for (int ks = 0; ks < KS; ++ks) {
        const int db = ks & 1;
        if (ks + 1 < KS) { GEMM_LOAD(ks + 1, db ^ 1); CP_WAIT(1); }
        else             { CP_WAIT(0); }
        __syncthreads();

        const uint32_t Ad_u = As_u + db * 128 * GSTR * 4;
        const uint32_t Bd_u = Bs_u + db * 128 * GSTR * 4;

#pragma unroll
        for (int kb = 0; kb < 4; ++kb) {
            uint32_t a[4][4], b[2][4];
#pragma unroll
            for (int mt = 0; mt < 4; ++mt)
                ldsm4(a[mt], Ad_u + a_lane + (uint32_t)(mt * 16 * GSTR + kb * 8) * 4);
#pragma unroll
            for (int ntp = 0; ntp < 2; ++ntp)
                ldsm4(b[ntp], Bd_u + b_lane + (uint32_t)(ntp * 16 * GSTR + kb * 8) * 4);
#pragma unroll
            for (int mt = 0; mt < 4; ++mt)
#pragma unroll
                for (int nt = 0; nt < 4; ++nt)
                    mma8(acc[mt][nt], a[mt], &b[nt >> 1][(nt & 1) * 2]);
        }
        __syncthreads();
    }

    const int row_base = blockIdx.y * 128 + wm * 64;
    const int col_base = blockIdx.x * 128 + wn * 32;
#pragma unroll
    for (int mt = 0; mt < 4; ++mt) {
        const int r0 = row_base + mt * 16 + lq;
#pragma unroll
        for (int nt = 0; nt < 4; ++nt) {
            const int cn = col_base + nt * 8 + ls * 2;
            const float2 bb = *(const float2*)(bias + cn);
            float2 o0, o1;
            o0.x = acc[mt][nt][0] + bb.x;  o0.y = acc[mt][nt][1] + bb.y;
            o1.x = acc[mt][nt][2] + bb.x;  o1.y = acc[mt][nt][3] + bb.y;
            *(float2*)(C + (size_t)r0 * N + cn)       = o0;
            *(float2*)(C + (size_t)(r0 + 8) * N + cn) = o1;
        }
    }
}

// ---------------------------------------------------------------------------
// RoPE + head scatter (unchanged).
// ---------------------------------------------------------------------------
__global__ __launch_bounds__(256) void rope_scatter(
    const float* __restrict__ qkv,
    float* __restrict__ qh, float* __restrict__ kh, float* __restrict__ vh,
    float* __restrict__ kout, float* __restrict__ vout)
{
    const int t = blockIdx.x * blockDim.x + threadIdx.x;
    const int d = t & 31;
    const int h = (t >> 5) & 15;
    const int l = (t >> 9) & 2047;
    const int b = t >> 20;

    const float* base = qkv + (size_t)(b * LL + l) * QKV_N;

    const float inv = __expf(-(float)d * (9.210340371976184f / 32.f));
    const float ang = (float)l * inv;
    float sn, cs;
    sincosf(ang, &sn, &cs);

    const size_t ob = ((size_t)((b * HH + h) * LL + l)) * HD;

    const float q1 = base[h*HD + d], q2 = base[h*HD + d + 32];
    qh[ob + d]      = __uint_as_float(f2tf((q1 * cs - q2 * sn) * 0.125f));
    qh[ob + d + 32] = __uint_as_float(f2tf((q1 * sn + q2 * cs) * 0.125f));

    const float k1 = base[DD + h*HD + d], k2 = base[DD + h*HD + d + 32];
    const float kr1 = k1 * cs - k2 * sn;
    const float kr2 = k1 * sn + k2 * cs;
    kout[ob + d]      = kr1;
    kout[ob + d + 32] = kr2;
    kh[ob + d]        = __uint_as_float(f2tf(kr1));
    kh[ob + d + 32]   = __uint_as_float(f2tf(kr2));

    const float v1 = base[2*DD + h*HD + d], v2 = base[2*DD + h*HD + d + 32];
    vout[ob + d]      = v1;
    vout[ob + d + 32] = v2;
    vh[ob + d]        = __uint_as_float(f2tf(v1));
    vh[ob + d + 32]   = __uint_as_float(f2tf(v2));
}

// ---------------------------------------------------------------------------
// Flash attention v6: Br=128, Bc=64, 256 threads (8 warps = 4 row x 2 col).
// Warp (wr=wid&3, wc=wid>>2): rows wr*32..+32, K-tokens wc*32..+32.
// 32-row warps halve the K/V fragment LDS amplification vs 16-row warps.
// Per-warp independent online softmax (4 row-pair stats); 2-way split-KV
// combine in the epilogue. Q register-resident.
// smem: Ks[2][64*FSTR] | Vt[2][64*FSTR] | Ps[8][32*PSTR] | cm[256] | cl[256]
// Epilogue 'ac' (128 x 66) aliases the Ks region (dead by then).
// ---------------------------------------------------------------------------
#define FSTR 68
#define PSTR 36
#define VT_OFF (2*64*FSTR)                  // 8704
#define PS_OFF (VT_OFF + 2*64*FSTR)         // 17408
#define CM_OFF (PS_OFF + 8*32*PSTR)         // 26624
#define CL_OFF (CM_OFF + 256)
#define FLASH_SMEM ((CL_OFF + 256) * 4)     // 108544 B

__global__ __launch_bounds__(256) void flash_mma(
    const float* __restrict__ Q, const float* __restrict__ K,
    const float* __restrict__ V, float* __restrict__ ctx)
{
    extern __shared__ float sm[];
    float* Ks = sm;
    float* Vt = sm + VT_OFF;
    float* Ps = sm + PS_OFF;
    float* cm = sm + CM_OFF;
    float* cl = sm + CL_OFF;
    float* ac = sm;                      // epilogue alias of Ks, stride 66
    const uint32_t Ks_u = smem_u32(Ks);
    const uint32_t Vt_u = smem_u32(Vt);
    const uint32_t Ps_u = smem_u32(Ps);

    const int qi   = gridDim.x - 1 - blockIdx.x;   // heavy tiles first
    const int bh   = blockIdx.y;
    const int tid  = threadIdx.x;
    const int lane = tid & 31;
    const int wid  = tid >> 5;           // 0..7
    const int wr   = wid & 3;            // row group (4 x 32 rows)
    const int wc   = wid >> 2;           // col group (2 x 32 tokens)
    const int lq   = lane >> 2;
    const int ls   = lane & 3;
    const int s    = lane >> 3;
    const int srow = lane & 7;
    const int row0 = wr * 32;            // warp's first row (0..96)

    // ldmatrix lane offsets (bytes)
    const uint32_t bk_lane =
        (uint32_t)(((s >> 1) * 8 + srow) * FSTR + (s & 1) * 4) * 4;
    const uint32_t ap_lane =
        (uint32_t)(((s & 1) * 8 + srow) * PSTR + (s >> 1) * 4) * 4;
    const uint32_t Psw_u = Ps_u + (uint32_t)(wid * 32 * PSTR) * 4;
    float* Psw = Ps + wid * 32 * PSTR;

    const float* Qb = Q + ((size_t)bh * LL + qi * 128) * HD;
    const float* Kb = K + (size_t)bh * LL * HD;
    const float* Vb = V + (size_t)bh * LL * HD;

    // K tile loader: 64x64 floats, 256 threads -> 4 cp.async each
#define FL_LOAD_K(dst_u, src)                                                 \
    {                                                                         \
        _Pragma("unroll")                                                     \
        for (int i = 0; i < 4; ++i) {                                         \
            const int c   = tid + i * 256;                                    \
            const int row = c >> 4;                                           \
            const int cc  = (c & 15) * 4;                                     \
            CP16((dst_u) + (uint32_t)(row * FSTR + cc) * 4,                   \
                 (src) + (size_t)row * HD + cc);                              \
        }                                                                     \
    }

    const int vtok  = tid & 63;          // token within 64-token tile
    const int vhalf = tid >> 6;          // 0..3 -> 16 dims each

    float4 vr[4];
#define FL_LDG_V(jt)                                                          \
    {                                                                         \
        const float* vb = Vb + ((size_t)(jt) * 64 + vtok) * HD + vhalf * 16;  \
        _Pragma("unroll")                                                     \
        for (int i = 0; i < 4; ++i) vr[i] = *(const float4*)(vb + i * 4);     \
    }

#define FL_STS_V(db)                                                          \
    {                                                                         \
        float* vt = Vt + (db) * 64 * FSTR;                                    \
        _Pragma("unroll")                                                     \
        for (int i = 0; i < 4; ++i) {                                         \
            const int c0 = vhalf * 16 + i * 4;                                \
            vt[(c0 + 0) * FSTR + vtok] = vr[i].x;                             \
            vt[(c0 + 1) * FSTR + vtok] = vr[i].y;                             \
            vt[(c0 + 2) * FSTR + vtok] = vr[i].z;                             \
            vt[(c0 + 3) * FSTR + vtok] = vr[i].w;                             \
        }                                                                     \
    }

    // prologue: K0 via cp.async, V0 via LDG, Q fragments from gmem
    FL_LOAD_K(Ks_u, Kb);
    CP_COMMIT();
    FL_LDG_V(0);

    uint32_t qf[8][2][4];                // [kb][mt][frag]
#pragma unroll
    for (int kb = 0; kb < 8; ++kb) {
        const int k = kb * 8 + ls;
#pragma unroll
        for (int mt = 0; mt < 2; ++mt) {
            const int r = row0 + mt * 16 + lq;
            qf[kb][mt][0] = __float_as_uint(Qb[(size_t)r * HD + k]);
            qf[kb][mt][1] = __float_as_uint(Qb[(size_t)(r + 8) * HD + k]);
            qf[kb][mt][2] = __float_as_uint(Qb[(size_t)r * HD + k + 4]);
            qf[kb][mt][3] = __float_as_uint(Qb[(size_t)(r + 8) * HD + k + 4]);
        }
    }

    float acc[2][8][4];
#pragma unroll
    for (int mt = 0; mt < 2; ++mt)
#pragma unroll
        for (int nt = 0; nt < 8; ++nt)
#pragma unroll
            for (int r = 0; r < 4; ++r) acc[mt][nt][r] = 0.f;
    float mm[4] = {-1e30f, -1e30f, -1e30f, -1e30f};
    float llv[4] = {0.f, 0.f, 0.f, 0.f};

    const int jtmax = 2 * qi + 1;

    for (int jt = 0; jt <= jtmax; ++jt) {
        const int db = jt & 1;
        CP_WAIT(0);
        FL_STS_V(db);
        __syncthreads();

        if (jt < jtmax) {
            FL_LOAD_K(Ks_u + (uint32_t)((db ^ 1) * 64 * FSTR) * 4,
                      Kb + (size_t)(jt + 1) * 64 * HD);
            CP_COMMIT();
            FL_LDG_V(jt + 1);
        }

        // ---- S = Q K^T on this warp's 32 tokens x 32 rows-pair groups ----
        float sc[2][4][4];
#pragma unroll
        for (int mt = 0; mt < 2; ++mt)
#pragma unroll
            for (int nt = 0; nt < 4; ++nt)
#pragma unroll
                for (int r = 0; r < 4; ++r) sc[mt][nt][r] = 0.f;

        const uint32_t Kd_u = Ks_u + (uint32_t)(db * 64 * FSTR) * 4
                            + (uint32_t)(wc * 32 * FSTR) * 4 + bk_lane;
#pragma unroll
        for (int kb = 0; kb < 8; ++kb) {
#pragma unroll
            for (int ntp = 0; ntp < 2; ++ntp) {
                uint32_t b[4];
                ldsm4(b, Kd_u + (uint32_t)(ntp * 16 * FSTR + kb * 8) * 4);
#pragma unroll
                for (int mt = 0; mt < 2; ++mt) {
                    mma8(sc[mt][ntp * 2],     qf[kb][mt], b);
                    mma8(sc[mt][ntp * 2 + 1], qf[kb][mt], b + 2);
                }
            }
        }

        // ---- causal mask (last two tiles) ----
        if (jt >= 2 * qi) {
            const int cbase = jt * 64 + wc * 32;
#pragma unroll
            for (int mt = 0; mt < 2; ++mt) {
                const int rg0 = qi * 128 + row0 + mt * 16 + lq;
#pragma unroll
                for (int nt = 0; nt < 4; ++nt) {
                    const int cg = cbase + nt * 8 + ls * 2;
                    if (cg > rg0)         sc[mt][nt][0] += -1000000000.0f;
                    if (cg + 1 > rg0)     sc[mt][nt][1] += -1000000000.0f;
                    if (cg > rg0 + 8)     sc[mt][nt][2] += -1000000000.0f;
                    if (cg + 1 > rg0 + 8) sc[mt][nt][3] += -1000000000.0f;
                }
            }
        }

        // ---- row max per row-pair group (quad shfl) ----
        float mx[4];
#pragma unroll
        for (int mt = 0; mt < 2; ++mt) {
            float a0 = sc[mt][0][0], a1 = sc[mt][0][2];
#pragma unroll
            for (int nt = 0; nt < 4; ++nt) {
                a0 = fmaxf(a0, fmaxf(sc[mt][nt][0], sc[mt][nt][1]));
                a1 = fmaxf(a1, fmaxf(sc[mt][nt][2], sc[mt][nt][3]));
            }
            mx[mt * 2]     = a0;
            mx[mt * 2 + 1] = a1;
        }
#pragma unroll
        for (int i = 0; i < 4; ++i) {
            mx[i] = fmaxf(mx[i], __shfl_xor_sync(0xffffffffu, mx[i], 1));
            mx[i] = fmaxf(mx[i], __shfl_xor_sync(0xffffffffu, mx[i], 2));
        }

        float al[4];
#pragma unroll
        for (int i = 0; i < 4; ++i) {
            const float mn = fmaxf(mm[i], mx[i]);
            al[i] = __expf(mm[i] - mn);
            mm[i] = mn;
        }

        // ---- P = exp(S - m), round, store to own Ps slice; row sums ----
        float rs[4] = {0.f, 0.f, 0.f, 0.f};
#pragma unroll
        for (int mt = 0; mt < 2; ++mt) {
            const float mn0 = mm[mt * 2], mn1 = mm[mt * 2 + 1];
#pragma unroll
            for (int nt = 0; nt < 4; ++nt) {
                const float p0 = __expf(sc[mt][nt][0] - mn0);
                const float p1 = __expf(sc[mt][nt][1] - mn0);
                const float p2 = __expf(sc[mt][nt][2] - mn1);
                const float p3 = __expf(sc[mt][nt][3] - mn1);
                rs[mt * 2]     += p0 + p1;
                rs[mt * 2 + 1] += p2 + p3;
                uint2 w0, w1;
                w0.x = f2tf(p0); w0.y = f2tf(p1);
                w1.x = f2tf(p2); w1.y = f2tf(p3);
                const int cc = nt * 8 + ls * 2;
                *(uint2*)(Psw + (mt * 16 + lq) * PSTR + cc)     = w0;
                *(uint2*)(Psw + (mt * 16 + lq + 8) * PSTR + cc) = w1;
            }
        }
#pragma unroll
        for (int i = 0; i < 4; ++i) {
            rs[i] += __shfl_xor_sync(0xffffffffu, rs[i], 1);
            rs[i] += __shfl_xor_sync(0xffffffffu, rs[i], 2);
            llv[i] = llv[i] * al[i] + rs[i];
        }

#pragma unroll
        for (int mt = 0; mt < 2; ++mt)
#pragma unroll
            for (int nt = 0; nt < 8; ++nt) {
                acc[mt][nt][0] *= al[mt * 2];     acc[mt][nt][1] *= al[mt * 2];
                acc[mt][nt][2] *= al[mt * 2 + 1]; acc[mt][nt][3] *= al[mt * 2 + 1];
            }
        __syncwarp();                    // Ps slice visible to own ldmatrix

        // ---- O += P V over this warp's 32 tokens, full 64 head dims ----
        const uint32_t Vd_u = Vt_u + (uint32_t)(db * 64 * FSTR) * 4 + bk_lane;
#pragma unroll
        for (int kb = 0; kb < 4; ++kb) {
            uint32_t a[2][4];
#pragma unroll
            for (int mt = 0; mt < 2; ++mt)
                ldsm4(a[mt], Psw_u + ap_lane +
                      (uint32_t)(mt * 16 * PSTR + kb * 8) * 4);
#pragma unroll
            for (int ntp = 0; ntp < 4; ++ntp) {
                uint32_t b[4];
                ldsm4(b, Vd_u +
                      (uint32_t)(ntp * 16 * FSTR + wc * 32 + kb * 8) * 4);
#pragma unroll
                for (int mt = 0; mt < 2; ++mt) {
                    mma8(acc[mt][ntp * 2],     a[mt], b);
                    mma8(acc[mt][ntp * 2 + 1], a[mt], b + 2);
                }
            }
        }
        __syncwarp();
    }

    // ---- epilogue: 2-way split-KV combine across the two column groups ----
    if (ls == 0) {
#pragma unroll
        for (int mt = 0; mt < 2; ++mt) {
            cm[wc * 128 + row0 + mt * 16 + lq]     = mm[mt * 2];
            cm[wc * 128 + row0 + mt * 16 + lq + 8] = mm[mt * 2 + 1];
            cl[wc * 128 + row0 + mt * 16 + lq]     = llv[mt * 2];
            cl[wc * 128 + row0 + mt * 16 + lq + 8] = llv[mt * 2 + 1];
        }
    }
    __syncthreads();                     // also fences all loop smem reads

    float sS[4], lt[4];
#pragma unroll
    for (int i = 0; i < 4; ++i) {
        const int row = row0 + (i >> 1) * 16 + (i & 1) * 8 + lq;
        const float mo = cm[(wc ^ 1) * 128 + row];
        const float lo = cl[(wc ^ 1) * 128 + row];
        const float M  = fmaxf(mm[i], mo);
        sS[i] = __expf(mm[i] - M);
        lt[i] = llv[i] * sS[i] + lo * __expf(mo - M);
    }

    if (wc == 1) {                       // publish scaled partial O
#pragma unroll
        for (int mt = 0; mt < 2; ++mt) {
            const int r = row0 + mt * 16 + lq;
#pragma unroll
            for (int nt = 0; nt < 8; ++nt) {
                const int cc = nt * 8 + ls * 2;
                float2 w0, w1;
                w0.x = acc[mt][nt][0] * sS[mt * 2];
                w0.y = acc[mt][nt][1] * sS[mt * 2];
                w1.x = acc[mt][nt][2] * sS[mt * 2 + 1];
                w1.y = acc[mt][nt][3] * sS[mt * 2 + 1];
                *(float2*)(ac + r * 66 + cc)       = w0;
                *(float2*)(ac + (r + 8) * 66 + cc) = w1;
            }
        }
    }
    __syncthreads();

    if (wc == 0) {
        const int b = bh >> 4;
        const int h = bh & 15;
#pragma unroll
        for (int mt = 0; mt < 2; ++mt) {
            const float inv0 = 1.f / lt[mt * 2];
            const float inv1 = 1.f / lt[mt * 2 + 1];
            const int r  = row0 + mt * 16 + lq;
            const int rg = qi * 128 + r;
#pragma unroll
            for (int nt = 0; nt < 8; ++nt) {
                const int cc = nt * 8 + ls * 2;
                const float2 p0 = *(const float2*)(ac + r * 66 + cc);
                const float2 p1 = *(const float2*)(ac + (r + 8) * 66 + cc);
                const int cn = h * HD + cc;
                uint2 o0, o1;
                o0.x = f2tf((acc[mt][nt][0] * sS[mt * 2] + p0.x) * inv0);
                o0.y = f2tf((acc[mt][nt][1] * sS[mt * 2] + p0.y) * inv0);
                o1.x = f2tf((acc[mt][nt][2] * sS[mt * 2 + 1] + p1.x) * inv1);
                o1.y = f2tf((acc[mt][nt][3] * sS[mt * 2 + 1] + p1.y) * inv1);
                *(uint2*)(ctx + (size_t)(b * LL + rg) * DD + cn)     = o0;
                *(uint2*)(ctx + (size_t)(b * LL + rg + 8) * DD + cn) = o1;
            }
        }
    }
}

// ---------------------------------------------------------------------------
// Launch
// ---------------------------------------------------------------------------
extern "C" void kernel_launch(void* const* d_in, const int* in_sizes, int n_in,
                              void* d_out, int out_size)
{
    const float* x       = (const float*)d_in[0];
    const float* Wqkv_w  = (const float*)d_in[2];
    const float* Wqkv_b  = (const float*)d_in[3];
    const float* Wout_w  = (const float*)d_in[4];
    const float* Wout_b  = (const float*)d_in[5];

    float* out  = (float*)d_out;
    float* kout = out + BLD;
    float* vout = kout + BLD;

    float *xr, *wqkv, *wout_r, *qkv, *qh, *kh, *vh, *ctx;
    cudaGetSymbolAddress((void**)&xr,     g_xr);
    cudaGetSymbolAddress((void**)&wqkv,   g_wqkv);
    cudaGetSymbolAddress((void**)&wout_r, g_wout);
    cudaGetSymbolAddress((void**)&qkv,    g_qkv);
    cudaGetSymbolAddress((void**)&qh,     g_q);
    cudaGetSymbolAddress((void**)&kh,     g_k);
    cudaGetSymbolAddress((void**)&vh,     g_v);
    cudaGetSymbolAddress((void**)&ctx,    g_ctx);

    cudaFuncSetAttribute(gemm_mma,
                         cudaFuncAttributeMaxDynamicSharedMemorySize, GEMM_SMEM);
    cudaFuncSetAttribute(flash_mma,
                         cudaFuncAttributeMaxDynamicSharedMemorySize, FLASH_SMEM);

    round_all<<<(RND_TOTAL4 + 255) / 256, 256>>>(
        (const float4*)x, (float4*)xr,
        (const float4*)Wqkv_w, (float4*)wqkv,
        (const float4*)Wout_w, (float4*)wout_r);

    gemm_mma<<<dim3(QKV_N / 128, ROWS / 128), 256, GEMM_SMEM>>>(
        xr, wqkv, Wqkv_b, qkv, QKV_N, DD);

    rope_scatter<<<(BB * LL * HH * 32) / 256, 256>>>(qkv, qh, kh, vh, kout, vout);

    flash_mma<<<dim3(LL / 128, BB * HH), 256, FLASH_SMEM>>>(qh, kh, vh, ctx);

    gemm_mma<<<dim3(DD / 128, ROWS / 128), 256, GEMM_SMEM>>>(
        ctx, wout_r, Wout_b, out, DD, DD);
}